// round 15
// baseline (speedup 1.0000x reference)
#include <cuda_runtime.h>
#include <cuda_bf16.h>
#include <mma.h>
#include <cstdint>

#define B_SZ 64
#define T_SZ 2048
#define K_SZ 256      // U_dim == X_dim
#define UN   256      // units

static __device__ __forceinline__ float softsign_exact(float z) {
    return z / (1.0f + fabsf(z));
}

#define BAR_SYNC(id, cnt)   asm volatile("bar.sync %0, %1;"   :: "r"(id), "r"(cnt) : "memory")
#define BAR_ARRIVE(id, cnt) asm volatile("bar.arrive %0, %1;" :: "r"(id), "r"(cnt) : "memory")

// ======= single fused kernel: GEMM + softsign scan + all GEMV epilogues =======
// 128 CTAs: b = blockIdx.x>>1, n0 = (blockIdx.x&1)*128. blockDim=384:
//   tid [0,256)   : GEMM warps (32x32 tiles, grid 2x4)
//   tid [256,320) : staging warps (A fp32->bf16->STS; +A_lo/Wlo in precise steps)
//   tid [320,384) : scan warps (2 u-chains per thread) + I0 + output GEMVs
// Heterogeneous steps: 30 imprecise chunks x 2 steps of KC=128 (Xhi*Whi only) +
// 2 precise chunks x 4 steps of KC=64 (full 3-term split). Softsign contraction
// annihilates imprecise-era rounding error before Ys[-1].
// Barriers: A_READY[buf]=6+buf (320), A_FREE[buf]=8+buf (320),
//           OUT_READY[buf]=2+buf (320), OUT_FREE[buf]=4+buf (320).
// Each: exactly one arrive-phase per sync-phase (overrun-proof).
#define TM 64
#define A_LD 136     // 128 + 8 pad (hi buffer, KC=128 capable)
#define A_LO_LD 72   // 64 + 8 pad (lo buffer, KC=64 only)
#define B_LD 136     // 128 + 8 pad
#define O_LD 136

#define A_HI_HALF (TM * A_LD * 2)         // 17408 B
#define A_LO_HALF (TM * A_LO_LD * 2)      // 9216 B
#define BLO_BUF   (64 * B_LD * 2)         // 17408 B (one KC=64 Wlo chunk)
#define OFF_BHI 0                          // 69632
#define OFF_BLO 69632                      // 2 bufs -> 34816
#define OFF_AHI 104448                     // 2 bufs -> 34816
#define OFF_ALO 139264                     // 2 bufs -> 18432
#define OFF_OUT 157696                     // 2 x 64*136*4 = 69632
#define OUT_ELE (TM * O_LD)
#define FUSED_SMEM 227328

#define NCHUNK 32
#define PRECISE_C 30
#define NSTEP 68       // 30*2 (KC=128) + 2*4 (KC=64)

static __device__ __forceinline__ void split4(float4 v, uint2& hv, uint2& lv) {
    __nv_bfloat162 h01, h23, l01, l23;
    h01.x = __float2bfloat16(v.x); h01.y = __float2bfloat16(v.y);
    h23.x = __float2bfloat16(v.z); h23.y = __float2bfloat16(v.w);
    l01.x = __float2bfloat16(v.x - __bfloat162float(h01.x));
    l01.y = __float2bfloat16(v.y - __bfloat162float(h01.y));
    l23.x = __float2bfloat16(v.z - __bfloat162float(h23.x));
    l23.y = __float2bfloat16(v.w - __bfloat162float(h23.y));
    hv.x = *reinterpret_cast<uint32_t*>(&h01);
    hv.y = *reinterpret_cast<uint32_t*>(&h23);
    lv.x = *reinterpret_cast<uint32_t*>(&l01);
    lv.y = *reinterpret_cast<uint32_t*>(&l23);
}
static __device__ __forceinline__ uint2 pack_hi4(float4 v) {
    __nv_bfloat162 h01, h23;
    h01.x = __float2bfloat16(v.x); h01.y = __float2bfloat16(v.y);
    h23.x = __float2bfloat16(v.z); h23.y = __float2bfloat16(v.w);
    uint2 r;
    r.x = *reinterpret_cast<uint32_t*>(&h01);
    r.y = *reinterpret_cast<uint32_t*>(&h23);
    return r;
}
static __device__ __forceinline__ uint2 pack_lo4(float4 v) {
    __nv_bfloat162 l01, l23;
    l01.x = __float2bfloat16(v.x - __bfloat162float(__float2bfloat16(v.x)));
    l01.y = __float2bfloat16(v.y - __bfloat162float(__float2bfloat16(v.y)));
    l23.x = __float2bfloat16(v.z - __bfloat162float(__float2bfloat16(v.z)));
    l23.y = __float2bfloat16(v.w - __bfloat162float(__float2bfloat16(v.w)));
    uint2 r;
    r.x = *reinterpret_cast<uint32_t*>(&l01);
    r.y = *reinterpret_cast<uint32_t*>(&l23);
    return r;
}

// step decode: returns chunk c, k-offset kbase, k-length klen, precise flag,
// and whether this step ends its chunk.
static __device__ __forceinline__ void step_decode(int step, int& c, int& kbase,
                                                   int& klen, bool& precise,
                                                   bool& chunk_end) {
    if (step < 60) {
        c = step >> 1;
        kbase = (step & 1) * 128;
        klen = 128;
        precise = false;
        chunk_end = (step & 1) == 1;
    } else {
        int s2 = step - 60;
        c = PRECISE_C + (s2 >> 2);
        kbase = (s2 & 3) * 64;
        klen = 64;
        precise = true;
        chunk_end = (s2 & 3) == 3;
    }
}

__global__ void __launch_bounds__(384, 1) fused_kernel(
        const float* __restrict__ U,
        const float* __restrict__ X,
        const float* __restrict__ W_i,
        const float* __restrict__ R_0,
        const float* __restrict__ b_0,
        const float* __restrict__ R_z,
        const float* __restrict__ b_z,
        const float* __restrict__ R_b,
        const float* __restrict__ W_p,
        const float* __restrict__ W_d,
        float* __restrict__ out) {
    using namespace nvcuda;
    extern __shared__ __align__(16) char smc[];
    __nv_bfloat16* const Bhi  = reinterpret_cast<__nv_bfloat16*>(smc + OFF_BHI);
    float*         const outs = reinterpret_cast<float*>(smc + OFF_OUT);

    const int tid = threadIdx.x;
    const int b   = blockIdx.x >> 1;
    const int n0  = (blockIdx.x & 1) * 128;
    const float* const Xb = X + (size_t)b * T_SZ * K_SZ;

    // ---- stage resident W_hi half (warps 0-9; scan warps do I0) ----
    if (tid < 320) {
        for (int idx = tid; idx < K_SZ * 32; idx += 320) {   // 8192 float4
            int row = idx >> 5, c4 = idx & 31;
            float4 v = *reinterpret_cast<const float4*>(W_i + (size_t)row * UN + n0 + c4 * 4);
            *reinterpret_cast<uint2*>(&Bhi[row * B_LD + c4 * 4]) = pack_hi4(v);
        }
    }
    __syncthreads();

    if (tid < 256) {
        // ======================= GEMM warps (pure compute) =======================
        const int wid = tid >> 5;
        const int wm  = wid >> 2;        // 0..1 : rows of 32
        const int wn  = wid & 3;         // 0..3 : cols of 32

        wmma::fragment<wmma::accumulator, 16, 16, 16, float> acc[2][2];
        #pragma unroll
        for (int i = 0; i < 2; i++)
            #pragma unroll
            for (int j = 0; j < 2; j++) wmma::fill_fragment(acc[i][j], 0.0f);

        #pragma unroll 1
        for (int step = 0; step < NSTEP; step++) {
            int c, kbase, klen; bool precise, chunk_end;
            step_decode(step, c, kbase, klen, precise, chunk_end);
            const int abuf = step & 1;
            __nv_bfloat16* const Ah = reinterpret_cast<__nv_bfloat16*>(
                smc + OFF_AHI + abuf * A_HI_HALF);
            __nv_bfloat16* const Al = reinterpret_cast<__nv_bfloat16*>(
                smc + OFF_ALO + abuf * A_LO_HALF);
            __nv_bfloat16* const Bl = reinterpret_cast<__nv_bfloat16*>(
                smc + OFF_BLO + abuf * BLO_BUF);

            BAR_SYNC(6 + abuf, 320);     // A_READY[abuf]

            #pragma unroll 2
            for (int kk = 0; kk < klen; kk += 16) {
                const int krow = kbase + kk;
                wmma::fragment<wmma::matrix_a, 16, 16, 16, __nv_bfloat16, wmma::row_major> ah[2];
                wmma::fragment<wmma::matrix_b, 16, 16, 16, __nv_bfloat16, wmma::row_major> bh[2];
                #pragma unroll
                for (int i = 0; i < 2; i++)
                    wmma::load_matrix_sync(ah[i], &Ah[(wm * 32 + i * 16) * A_LD + kk], A_LD);
                #pragma unroll
                for (int j = 0; j < 2; j++)
                    wmma::load_matrix_sync(bh[j], &Bhi[krow * B_LD + wn * 32 + j * 16], B_LD);
                #pragma unroll
                for (int i = 0; i < 2; i++)
                    #pragma unroll
                    for (int j = 0; j < 2; j++)
                        wmma::mma_sync(acc[i][j], ah[i], bh[j], acc[i][j]);   // Xhi*Whi
                if (precise) {
                    wmma::fragment<wmma::matrix_a, 16, 16, 16, __nv_bfloat16, wmma::row_major> al[2];
                    wmma::fragment<wmma::matrix_b, 16, 16, 16, __nv_bfloat16, wmma::row_major> bl[2];
                    #pragma unroll
                    for (int i = 0; i < 2; i++)
                        wmma::load_matrix_sync(al[i], &Al[(wm * 32 + i * 16) * A_LO_LD + kk], A_LO_LD);
                    #pragma unroll
                    for (int j = 0; j < 2; j++)
                        wmma::load_matrix_sync(bl[j], &Bl[kk * B_LD + wn * 32 + j * 16], B_LD);
                    #pragma unroll
                    for (int i = 0; i < 2; i++)
                        #pragma unroll
                        for (int j = 0; j < 2; j++) {
                            wmma::mma_sync(acc[i][j], al[i], bh[j], acc[i][j]);   // Xlo*Whi
                            wmma::mma_sync(acc[i][j], ah[i], bl[j], acc[i][j]);   // Xhi*Wlo
                        }
                }
            }
            BAR_ARRIVE(8 + abuf, 320);   // A_FREE[abuf]

            if (chunk_end) {
                const int ob_buf = c & 1;
                if (c >= 2) BAR_SYNC(4 + ob_buf, 320);      // OUT_FREE[buf]
                float* ob = outs + ob_buf * OUT_ELE;
                #pragma unroll
                for (int i = 0; i < 2; i++)
                    #pragma unroll
                    for (int j = 0; j < 2; j++) {
                        wmma::store_matrix_sync(&ob[(wm * 32 + i * 16) * O_LD + wn * 32 + j * 16],
                                                acc[i][j], O_LD, wmma::mem_row_major);
                        wmma::fill_fragment(acc[i][j], 0.0f);
                    }
                BAR_ARRIVE(2 + ob_buf, 320);                // OUT_READY[buf]
            }
        }
    } else if (tid < 320) {
        // =========== staging warps: A hi (always), A lo + Wlo (precise) ===========
        const int st = tid - 256;        // 0..63

        #pragma unroll 1
        for (int step = 0; step < NSTEP; step++) {
            int c, kbase, klen; bool precise, chunk_end;
            step_decode(step, c, kbase, klen, precise, chunk_end);
            const int abuf = step & 1;
            __nv_bfloat16* const Ah = reinterpret_cast<__nv_bfloat16*>(
                smc + OFF_AHI + abuf * A_HI_HALF);
            __nv_bfloat16* const Al = reinterpret_cast<__nv_bfloat16*>(
                smc + OFF_ALO + abuf * A_LO_HALF);
            __nv_bfloat16* const Bl = reinterpret_cast<__nv_bfloat16*>(
                smc + OFF_BLO + abuf * BLO_BUF);

            if (step >= 2) BAR_SYNC(8 + abuf, 320);   // A_FREE[abuf]

            const float* const xsrc = Xb + (size_t)(c * TM) * K_SZ + kbase;
            if (!precise) {
                // 64 rows x 128 cols fp32 = 2048 float4; 32 per thread
                #pragma unroll 8
                for (int it = 0; it < 32; it++) {
                    int i = it * 64 + st;
                    int row = i >> 5, c4 = i & 31;
                    float4 v = *reinterpret_cast<const float4*>(
                        xsrc + (size_t)row * K_SZ + c4 * 4);
                    *reinterpret_cast<uint2*>(&Ah[row * A_LD + c4 * 4]) = pack_hi4(v);
                }
            } else {
                // X: 64 rows x 64 cols = 1024 float4; 16 per thread (hi+lo)
                #pragma unroll 8
                for (int it = 0; it < 16; it++) {
                    int i = it * 64 + st;
                    int row = i >> 4, c4 = i & 15;
                    float4 v = *reinterpret_cast<const float4*>(
                        xsrc + (size_t)row * K_SZ + c4 * 4);
                    uint2 hv, lv;
                    split4(v, hv, lv);
                    *reinterpret_cast<uint2*>(&Ah[row * A_LD + c4 * 4])    = hv;
                    *reinterpret_cast<uint2*>(&Al[row * A_LO_LD + c4 * 4]) = lv;
                }
                // Wlo chunk: 64 k-rows x 128 n-cols = 2048 float4; 32 per thread
                #pragma unroll 8
                for (int it = 0; it < 32; it++) {
                    int i = it * 64 + st;
                    int row = i >> 5, cc = i & 31;
                    float4 w = *reinterpret_cast<const float4*>(
                        W_i + (size_t)(kbase + row) * UN + n0 + cc * 4);
                    *reinterpret_cast<uint2*>(&Bl[row * B_LD + cc * 4]) = pack_lo4(w);
                }
            }
            BAR_ARRIVE(6 + abuf, 320);                // A_READY[abuf]
        }
    } else {
        // ============ scan warps: I recurrence + I0 + all output GEMVs ============
        const int u0 = (tid - 320) * 2;   // 0,2,..,126 (local)
        const int ug = n0 + u0;           // global unit column (even)

        float Ia = b_0[ug];
        float Ib = b_0[ug + 1];
        {
            const float* R0c = R_0 + ug;            // R_0 is [K_SZ][512]
            const float* Ubp = U + (size_t)b * K_SZ;
            #pragma unroll 8
            for (int k = 0; k < K_SZ; k++) {
                float uv = Ubp[k];
                Ia = fmaf(uv, R0c[(size_t)k * 512],     Ia);
                Ib = fmaf(uv, R0c[(size_t)k * 512 + 1], Ib);
            }
        }

        float ub_a = 0.f, ub_b = 0.f;
        float zp_a = b_z[3 * ug],     zi_a = b_z[3 * ug + 1], zd_a = b_z[3 * ug + 2];
        float zp_b = b_z[3 * ug + 3], zi_b = b_z[3 * ug + 4], zd_b = b_z[3 * ug + 5];
        float p_a = 0.f, p_b = 0.f, d_a = 0.f, d_b = 0.f;
        const float* const Ubp = U + (size_t)b * K_SZ;
        const float* const xlp = Xb + (size_t)(T_SZ - 1) * K_SZ;
        const float* const xpp = Xb + (size_t)(T_SZ - 2) * K_SZ;

        #pragma unroll 1
        for (int c = 0; c < NCHUNK; c++) {
            const int ob_buf = c & 1;
            BAR_SYNC(2 + ob_buf, 320);                      // OUT_READY[buf]
            const float* ob = outs + ob_buf * OUT_ELE;
            const float2* obp = reinterpret_cast<const float2*>(ob) + (u0 >> 1);
            float2 v  = obp[0];
            float2 vn = obp[O_LD / 2];
            #pragma unroll 8
            for (int t = 0; t < TM; t++) {
                float za = Ia + v.x;
                float zb = Ib + v.y;
                v = vn;
                if (t + 2 < TM) vn = obp[(size_t)(t + 2) * (O_LD / 2)];
                Ia = __fdividef(za, 1.0f + fabsf(za));
                Ib = __fdividef(zb, 1.0f + fabsf(zb));
            }
            BAR_ARRIVE(4 + ob_buf, 320);                    // OUT_FREE[buf]

            // ---- epilogue k-slice [8c, 8c+8) (hidden in scan slack) ----
            #pragma unroll
            for (int kk = 0; kk < 8; kk++) {
                const int k = c * 8 + kk;
                float uv  = Ubp[k];
                float xlv = xlp[k];
                float dxv = xlv - xpp[k];
                float2 rb  = *reinterpret_cast<const float2*>(R_b + (size_t)k * UN + ug);
                float2 rz0 = *reinterpret_cast<const float2*>(R_z + (size_t)k * 768 + 3 * ug);
                float2 rz1 = *reinterpret_cast<const float2*>(R_z + (size_t)k * 768 + 3 * ug + 2);
                float2 rz2 = *reinterpret_cast<const float2*>(R_z + (size_t)k * 768 + 3 * ug + 4);
                float2 wp  = *reinterpret_cast<const float2*>(W_p + (size_t)k * UN + ug);
                float2 wd  = *reinterpret_cast<const float2*>(W_d + (size_t)k * UN + ug);
                ub_a = fmaf(uv, rb.x, ub_a);   ub_b = fmaf(uv, rb.y, ub_b);
                zp_a = fmaf(uv, rz0.x, zp_a);  zi_a = fmaf(uv, rz0.y, zi_a);
                zd_a = fmaf(uv, rz1.x, zd_a);  zp_b = fmaf(uv, rz1.y, zp_b);
                zi_b = fmaf(uv, rz2.x, zi_b);  zd_b = fmaf(uv, rz2.y, zd_b);
                p_a  = fmaf(xlv, wp.x, p_a);   p_b  = fmaf(xlv, wp.y, p_b);
                d_a  = fmaf(dxv, wd.x, d_a);   d_b  = fmaf(dxv, wd.y, d_b);
            }
        }

        float Pa = softsign_exact(ub_a + p_a);
        float Pb = softsign_exact(ub_b + p_b);
        float Da = softsign_exact(d_a);
        float Db = softsign_exact(d_b);
        float2 r;
        r.x = zp_a * Pa + zi_a * Ia + zd_a * Da;
        r.y = zp_b * Pb + zi_b * Ib + zd_b * Db;
        *reinterpret_cast<float2*>(out + (size_t)b * UN + ug) = r;
    }
}

// ---------------- launcher ----------------
extern "C" void kernel_launch(void* const* d_in, const int* in_sizes, int n_in,
                              void* d_out, int out_size) {
    const float* U   = (const float*)d_in[0];
    const float* X   = (const float*)d_in[1];
    const float* R_z = (const float*)d_in[2];
    const float* b_z = (const float*)d_in[3];
    const float* R_0 = (const float*)d_in[4];
    const float* b_0 = (const float*)d_in[5];
    const float* R_b = (const float*)d_in[6];
    const float* W_p = (const float*)d_in[7];
    const float* W_i = (const float*)d_in[8];
    const float* W_d = (const float*)d_in[9];
    float* out = (float*)d_out;

    cudaFuncSetAttribute(fused_kernel,
                         cudaFuncAttributeMaxDynamicSharedMemorySize, FUSED_SMEM);

    fused_kernel<<<2 * B_SZ, 384, FUSED_SMEM>>>(U, X, W_i, R_0, b_0,
                                                R_z, b_z, R_b, W_p, W_d, out);
}

// round 16
// speedup vs baseline: 1.3039x; 1.3039x over previous
#include <cuda_runtime.h>
#include <cuda_bf16.h>
#include <mma.h>
#include <cstdint>

#define B_SZ 64
#define T_SZ 2048
#define K_SZ 256      // U_dim == X_dim
#define UN   256      // units

static __device__ __forceinline__ float softsign_exact(float z) {
    return z / (1.0f + fabsf(z));
}

#define BAR_SYNC(id, cnt)   asm volatile("bar.sync %0, %1;"   :: "r"(id), "r"(cnt) : "memory")
#define BAR_ARRIVE(id, cnt) asm volatile("bar.arrive %0, %1;" :: "r"(id), "r"(cnt) : "memory")

// ======= single fused kernel: GEMM + softsign scan + all GEMV epilogues =======
// 128 CTAs: b = blockIdx.x>>1, n0 = (blockIdx.x&1)*128. blockDim=384:
//   tid [0,256)   : GEMM warps (32x32 tiles, grid 2x4), KC=64 per step
//   tid [256,320) : staging warps (A hi always; A_lo + Wlo in precise steps)
//   tid [320,384) : scan warps (2 u-chains per thread) + I0 + output GEMVs
// A_hi is TRIPLE buffered (slot s%3) to break the 2-deep lockstep chain:
// staging for step s+3 depends on GEMM step s, so GEMM runs back-to-back.
// Precision: chunks < PRECISE_C use Xhi*Whi only (softsign contraction kills
// old rounding error); last 2 chunks (steps 120..127) add Xlo*Whi + Xhi*Wlo
// via a separate 2-deep protocol for A_lo/B_lo.
// Barriers (all count 320, one arrive-phase per sync-phase):
//   OUT_READY[b]=2+b, OUT_FREE[b]=4+b, A_READY[s%3]=6+s%3, A_FREE[s%3]=9+s%3,
//   PREADY[ps&1]=12+(ps&1), PFREE[ps&1]=14+(ps&1).
#define TM 64
#define KC 64
#define A_LD 72      // 64 + 8 pad
#define B_LD 136     // 128 + 8 pad
#define O_LD 136

#define A_HALF  (TM * A_LD * 2)           // 9216 B
#define BLO_BUF (KC * B_LD * 2)           // 17408 B
#define OFF_BHI 0                          // 69632
#define OFF_BLO 69632                      // 2 bufs -> 34816
#define OFF_AHI 104448                     // 3 bufs -> 27648
#define OFF_ALO 132096                     // 2 bufs -> 18432
#define OFF_OUT 150528                     // 2 x 64*136*4 = 69632
#define OUT_ELE (TM * O_LD)
#define FUSED_SMEM 220160

#define NCHUNK (T_SZ / TM)        // 32
#define NKC    (K_SZ / KC)        // 4
#define NSTEP  (NCHUNK * NKC)     // 128
#define PRECISE_C (NCHUNK - 2)    // chunks >= this use full 3-term split
#define PSTART (PRECISE_C * NKC)  // 120: first precise step

static __device__ __forceinline__ void split4(float4 v, uint2& hv, uint2& lv) {
    __nv_bfloat162 h01, h23, l01, l23;
    h01.x = __float2bfloat16(v.x); h01.y = __float2bfloat16(v.y);
    h23.x = __float2bfloat16(v.z); h23.y = __float2bfloat16(v.w);
    l01.x = __float2bfloat16(v.x - __bfloat162float(h01.x));
    l01.y = __float2bfloat16(v.y - __bfloat162float(h01.y));
    l23.x = __float2bfloat16(v.z - __bfloat162float(h23.x));
    l23.y = __float2bfloat16(v.w - __bfloat162float(h23.y));
    hv.x = *reinterpret_cast<uint32_t*>(&h01);
    hv.y = *reinterpret_cast<uint32_t*>(&h23);
    lv.x = *reinterpret_cast<uint32_t*>(&l01);
    lv.y = *reinterpret_cast<uint32_t*>(&l23);
}
static __device__ __forceinline__ uint2 pack_hi4(float4 v) {
    __nv_bfloat162 h01, h23;
    h01.x = __float2bfloat16(v.x); h01.y = __float2bfloat16(v.y);
    h23.x = __float2bfloat16(v.z); h23.y = __float2bfloat16(v.w);
    uint2 r;
    r.x = *reinterpret_cast<uint32_t*>(&h01);
    r.y = *reinterpret_cast<uint32_t*>(&h23);
    return r;
}
static __device__ __forceinline__ uint2 pack_lo4(float4 v) {
    __nv_bfloat162 l01, l23;
    l01.x = __float2bfloat16(v.x - __bfloat162float(__float2bfloat16(v.x)));
    l01.y = __float2bfloat16(v.y - __bfloat162float(__float2bfloat16(v.y)));
    l23.x = __float2bfloat16(v.z - __bfloat162float(__float2bfloat16(v.z)));
    l23.y = __float2bfloat16(v.w - __bfloat162float(__float2bfloat16(v.w)));
    uint2 r;
    r.x = *reinterpret_cast<uint32_t*>(&l01);
    r.y = *reinterpret_cast<uint32_t*>(&l23);
    return r;
}

__global__ void __launch_bounds__(384, 1) fused_kernel(
        const float* __restrict__ U,
        const float* __restrict__ X,
        const float* __restrict__ W_i,
        const float* __restrict__ R_0,
        const float* __restrict__ b_0,
        const float* __restrict__ R_z,
        const float* __restrict__ b_z,
        const float* __restrict__ R_b,
        const float* __restrict__ W_p,
        const float* __restrict__ W_d,
        float* __restrict__ out) {
    using namespace nvcuda;
    extern __shared__ __align__(16) char smc[];
    __nv_bfloat16* const Bhi  = reinterpret_cast<__nv_bfloat16*>(smc + OFF_BHI);
    float*         const outs = reinterpret_cast<float*>(smc + OFF_OUT);

    const int tid = threadIdx.x;
    const int b   = blockIdx.x >> 1;
    const int n0  = (blockIdx.x & 1) * 128;
    const float* const Xb = X + (size_t)b * T_SZ * K_SZ;

    // ---- stage resident W_hi half (warps 0-9; scan warps do I0) ----
    if (tid < 320) {
        for (int idx = tid; idx < K_SZ * 32; idx += 320) {   // 8192 float4
            int row = idx >> 5, c4 = idx & 31;
            float4 v = *reinterpret_cast<const float4*>(W_i + (size_t)row * UN + n0 + c4 * 4);
            *reinterpret_cast<uint2*>(&Bhi[row * B_LD + c4 * 4]) = pack_hi4(v);
        }
    }
    __syncthreads();

    if (tid < 256) {
        // ======================= GEMM warps (pure compute) =======================
        const int wid = tid >> 5;
        const int wm  = wid >> 2;        // 0..1 : rows of 32
        const int wn  = wid & 3;         // 0..3 : cols of 32

        wmma::fragment<wmma::accumulator, 16, 16, 16, float> acc[2][2];
        #pragma unroll
        for (int i = 0; i < 2; i++)
            #pragma unroll
            for (int j = 0; j < 2; j++) wmma::fill_fragment(acc[i][j], 0.0f);

        int slot = 0;   // s % 3
        #pragma unroll 1
        for (int step = 0; step < NSTEP; step++) {
            const int c  = step >> 2;
            const int kc = step & 3;
            const bool precise = (step >= PSTART);
            const int ps = step - PSTART;
            __nv_bfloat16* const Ah = reinterpret_cast<__nv_bfloat16*>(
                smc + OFF_AHI + slot * A_HALF);

            BAR_SYNC(6 + slot, 320);                 // A_READY[slot]
            if (precise) BAR_SYNC(12 + (ps & 1), 320);   // PREADY

            const __nv_bfloat16* const Al = reinterpret_cast<const __nv_bfloat16*>(
                smc + OFF_ALO + (ps & 1) * A_HALF);
            const __nv_bfloat16* const Bl = reinterpret_cast<const __nv_bfloat16*>(
                smc + OFF_BLO + (ps & 1) * BLO_BUF);

            #pragma unroll
            for (int kk = 0; kk < KC; kk += 16) {
                const int krow = kc * KC + kk;
                wmma::fragment<wmma::matrix_a, 16, 16, 16, __nv_bfloat16, wmma::row_major> ah[2];
                wmma::fragment<wmma::matrix_b, 16, 16, 16, __nv_bfloat16, wmma::row_major> bh[2];
                #pragma unroll
                for (int i = 0; i < 2; i++)
                    wmma::load_matrix_sync(ah[i], &Ah[(wm * 32 + i * 16) * A_LD + kk], A_LD);
                #pragma unroll
                for (int j = 0; j < 2; j++)
                    wmma::load_matrix_sync(bh[j], &Bhi[krow * B_LD + wn * 32 + j * 16], B_LD);
                #pragma unroll
                for (int i = 0; i < 2; i++)
                    #pragma unroll
                    for (int j = 0; j < 2; j++)
                        wmma::mma_sync(acc[i][j], ah[i], bh[j], acc[i][j]);   // Xhi*Whi
                if (precise) {
                    wmma::fragment<wmma::matrix_a, 16, 16, 16, __nv_bfloat16, wmma::row_major> al[2];
                    wmma::fragment<wmma::matrix_b, 16, 16, 16, __nv_bfloat16, wmma::row_major> bl[2];
                    #pragma unroll
                    for (int i = 0; i < 2; i++)
                        wmma::load_matrix_sync(al[i], &Al[(wm * 32 + i * 16) * A_LD + kk], A_LD);
                    #pragma unroll
                    for (int j = 0; j < 2; j++)
                        wmma::load_matrix_sync(bl[j], &Bl[kk * B_LD + wn * 32 + j * 16], B_LD);
                    #pragma unroll
                    for (int i = 0; i < 2; i++)
                        #pragma unroll
                        for (int j = 0; j < 2; j++) {
                            wmma::mma_sync(acc[i][j], al[i], bh[j], acc[i][j]);   // Xlo*Whi
                            wmma::mma_sync(acc[i][j], ah[i], bl[j], acc[i][j]);   // Xhi*Wlo
                        }
                }
            }
            BAR_ARRIVE(9 + slot, 320);               // A_FREE[slot]
            if (precise) BAR_ARRIVE(14 + (ps & 1), 320);  // PFREE

            if (kc == 3) {
                const int ob_buf = c & 1;
                if (c >= 2) BAR_SYNC(4 + ob_buf, 320);      // OUT_FREE[buf]
                float* ob = outs + ob_buf * OUT_ELE;
                #pragma unroll
                for (int i = 0; i < 2; i++)
                    #pragma unroll
                    for (int j = 0; j < 2; j++) {
                        wmma::store_matrix_sync(&ob[(wm * 32 + i * 16) * O_LD + wn * 32 + j * 16],
                                                acc[i][j], O_LD, wmma::mem_row_major);
                        wmma::fill_fragment(acc[i][j], 0.0f);
                    }
                BAR_ARRIVE(2 + ob_buf, 320);                // OUT_READY[buf]
            }
            slot = (slot == 2) ? 0 : slot + 1;
        }
    } else if (tid < 320) {
        // ============ staging warps: A_hi (3-deep); A_lo + Wlo when precise =======
        const int st = tid - 256;        // 0..63
        // A: 64 rows x 16 float4 per step; 16 per thread, prefetched
        int rowv[16], c4v[16];
        #pragma unroll
        for (int r = 0; r < 16; r++) {
            int i = r * 64 + st;
            rowv[r] = i >> 4;
            c4v[r]  = i & 15;
        }
        float4 xr[16];
        #pragma unroll
        for (int r = 0; r < 16; r++)
            xr[r] = *reinterpret_cast<const float4*>(
                Xb + (size_t)rowv[r] * K_SZ + c4v[r] * 4);

        int slot = 0;   // s % 3
        #pragma unroll 1
        for (int step = 0; step < NSTEP; step++) {
            const int kc = step & 3;
            const bool precise = (step >= PSTART);
            const int ps = step - PSTART;
            __nv_bfloat16* const Ah = reinterpret_cast<__nv_bfloat16*>(
                smc + OFF_AHI + slot * A_HALF);

            if (step >= 3) BAR_SYNC(9 + slot, 320);          // A_FREE[slot]
            if (precise && ps >= 2) BAR_SYNC(14 + (ps & 1), 320);  // PFREE

            if (precise) {
                __nv_bfloat16* const Al = reinterpret_cast<__nv_bfloat16*>(
                    smc + OFF_ALO + (ps & 1) * A_HALF);
                __nv_bfloat16* const Bl = reinterpret_cast<__nv_bfloat16*>(
                    smc + OFF_BLO + (ps & 1) * BLO_BUF);
                #pragma unroll
                for (int r = 0; r < 16; r++) {
                    uint2 hv, lv;
                    split4(xr[r], hv, lv);
                    *reinterpret_cast<uint2*>(&Ah[rowv[r] * A_LD + c4v[r] * 4]) = hv;
                    *reinterpret_cast<uint2*>(&Al[rowv[r] * A_LD + c4v[r] * 4]) = lv;
                }
                // Wlo chunk: 64 k-rows x 128 n-cols = 2048 float4; 32 per thread
                #pragma unroll 8
                for (int it = 0; it < 32; it++) {
                    int i = it * 64 + st;
                    int row = i >> 5, cc = i & 31;
                    float4 w = *reinterpret_cast<const float4*>(
                        W_i + (size_t)(kc * KC + row) * UN + n0 + cc * 4);
                    *reinterpret_cast<uint2*>(&Bl[row * B_LD + cc * 4]) = pack_lo4(w);
                }
                BAR_ARRIVE(12 + (ps & 1), 320);              // PREADY
            } else {
                #pragma unroll
                for (int r = 0; r < 16; r++)
                    *reinterpret_cast<uint2*>(&Ah[rowv[r] * A_LD + c4v[r] * 4]) = pack_hi4(xr[r]);
            }
            BAR_ARRIVE(6 + slot, 320);                       // A_READY[slot]

            if (step + 1 < NSTEP) {
                const int nc  = (step + 1) >> 2;
                const int nkc = (step + 1) & 3;
                const float* src = Xb + (size_t)(nc * TM) * K_SZ + nkc * KC;
                #pragma unroll
                for (int r = 0; r < 16; r++)
                    xr[r] = *reinterpret_cast<const float4*>(
                        src + (size_t)rowv[r] * K_SZ + c4v[r] * 4);
            }
            slot = (slot == 2) ? 0 : slot + 1;
        }
    } else {
        // ============ scan warps: I recurrence + I0 + all output GEMVs ============
        const int u0 = (tid - 320) * 2;   // 0,2,..,126 (local)
        const int ug = n0 + u0;           // global unit column (even)

        float Ia = b_0[ug];
        float Ib = b_0[ug + 1];
        {
            const float* R0c = R_0 + ug;            // R_0 is [K_SZ][512]
            const float* Ubp = U + (size_t)b * K_SZ;
            #pragma unroll 8
            for (int k = 0; k < K_SZ; k++) {
                float uv = Ubp[k];
                Ia = fmaf(uv, R0c[(size_t)k * 512],     Ia);
                Ib = fmaf(uv, R0c[(size_t)k * 512 + 1], Ib);
            }
        }

        float ub_a = 0.f, ub_b = 0.f;
        float zp_a = b_z[3 * ug],     zi_a = b_z[3 * ug + 1], zd_a = b_z[3 * ug + 2];
        float zp_b = b_z[3 * ug + 3], zi_b = b_z[3 * ug + 4], zd_b = b_z[3 * ug + 5];
        float p_a = 0.f, p_b = 0.f, d_a = 0.f, d_b = 0.f;
        const float* const Ubp = U + (size_t)b * K_SZ;
        const float* const xlp = Xb + (size_t)(T_SZ - 1) * K_SZ;
        const float* const xpp = Xb + (size_t)(T_SZ - 2) * K_SZ;

        #pragma unroll 1
        for (int c = 0; c < NCHUNK; c++) {
            const int ob_buf = c & 1;
            BAR_SYNC(2 + ob_buf, 320);                      // OUT_READY[buf]
            const float* ob = outs + ob_buf * OUT_ELE;
            const float2* obp = reinterpret_cast<const float2*>(ob) + (u0 >> 1);
            float2 v  = obp[0];
            float2 vn = obp[O_LD / 2];
            #pragma unroll 8
            for (int t = 0; t < TM; t++) {
                float za = Ia + v.x;
                float zb = Ib + v.y;
                v = vn;
                if (t + 2 < TM) vn = obp[(size_t)(t + 2) * (O_LD / 2)];
                Ia = __fdividef(za, 1.0f + fabsf(za));
                Ib = __fdividef(zb, 1.0f + fabsf(zb));
            }
            BAR_ARRIVE(4 + ob_buf, 320);                    // OUT_FREE[buf]

            // ---- epilogue k-slice [8c, 8c+8) (hidden in scan slack) ----
            #pragma unroll
            for (int kk = 0; kk < 8; kk++) {
                const int k = c * 8 + kk;
                float uv  = Ubp[k];
                float xlv = xlp[k];
                float dxv = xlv - xpp[k];
                float2 rb  = *reinterpret_cast<const float2*>(R_b + (size_t)k * UN + ug);
                float2 rz0 = *reinterpret_cast<const float2*>(R_z + (size_t)k * 768 + 3 * ug);
                float2 rz1 = *reinterpret_cast<const float2*>(R_z + (size_t)k * 768 + 3 * ug + 2);
                float2 rz2 = *reinterpret_cast<const float2*>(R_z + (size_t)k * 768 + 3 * ug + 4);
                float2 wp  = *reinterpret_cast<const float2*>(W_p + (size_t)k * UN + ug);
                float2 wd  = *reinterpret_cast<const float2*>(W_d + (size_t)k * UN + ug);
                ub_a = fmaf(uv, rb.x, ub_a);   ub_b = fmaf(uv, rb.y, ub_b);
                zp_a = fmaf(uv, rz0.x, zp_a);  zi_a = fmaf(uv, rz0.y, zi_a);
                zd_a = fmaf(uv, rz1.x, zd_a);  zp_b = fmaf(uv, rz1.y, zp_b);
                zi_b = fmaf(uv, rz2.x, zi_b);  zd_b = fmaf(uv, rz2.y, zd_b);
                p_a  = fmaf(xlv, wp.x, p_a);   p_b  = fmaf(xlv, wp.y, p_b);
                d_a  = fmaf(dxv, wd.x, d_a);   d_b  = fmaf(dxv, wd.y, d_b);
            }
        }

        float Pa = softsign_exact(ub_a + p_a);
        float Pb = softsign_exact(ub_b + p_b);
        float Da = softsign_exact(d_a);
        float Db = softsign_exact(d_b);
        float2 r;
        r.x = zp_a * Pa + zi_a * Ia + zd_a * Da;
        r.y = zp_b * Pb + zi_b * Ib + zd_b * Db;
        *reinterpret_cast<float2*>(out + (size_t)b * UN + ug) = r;
    }
}

// ---------------- launcher ----------------
extern "C" void kernel_launch(void* const* d_in, const int* in_sizes, int n_in,
                              void* d_out, int out_size) {
    const float* U   = (const float*)d_in[0];
    const float* X   = (const float*)d_in[1];
    const float* R_z = (const float*)d_in[2];
    const float* b_z = (const float*)d_in[3];
    const float* R_0 = (const float*)d_in[4];
    const float* b_0 = (const float*)d_in[5];
    const float* R_b = (const float*)d_in[6];
    const float* W_p = (const float*)d_in[7];
    const float* W_d = (const float*)d_in[8];
    const float* W_i = (const float*)d_in[8];
    const float* Wd2 = (const float*)d_in[9];
    (void)W_d;
    // metadata order: U, X, R_z, b_z, R_0, b_0, R_b, W_p, W_i, W_d
    const float* Wp_ = (const float*)d_in[7];
    const float* Wi_ = (const float*)d_in[8];
    const float* Wd_ = (const float*)d_in[9];
    float* out = (float*)d_out;

    cudaFuncSetAttribute(fused_kernel,
                         cudaFuncAttributeMaxDynamicSharedMemorySize, FUSED_SMEM);

    fused_kernel<<<2 * B_SZ, 384, FUSED_SMEM>>>(U, X, Wi_, R_0, b_0,
                                                R_z, b_z, R_b, Wp_, Wd_, out);
}

// round 17
// speedup vs baseline: 1.3380x; 1.0262x over previous
#include <cuda_runtime.h>
#include <cuda_bf16.h>
#include <mma.h>
#include <cstdint>

#define B_SZ 64
#define T_SZ 2048
#define K_SZ 256      // U_dim == X_dim
#define UN   256      // units

static __device__ __forceinline__ float softsign_exact(float z) {
    return z / (1.0f + fabsf(z));
}

#define BAR_SYNC(id, cnt)   asm volatile("bar.sync %0, %1;"   :: "r"(id), "r"(cnt) : "memory")
#define BAR_ARRIVE(id, cnt) asm volatile("bar.arrive %0, %1;" :: "r"(id), "r"(cnt) : "memory")

// ======= single fused kernel: GEMM + softsign scan + all GEMV epilogues =======
// 128 CTAs: b = blockIdx.x>>1, n0 = (blockIdx.x&1)*128. blockDim=448:
//   tid [0,256)   : 8 GEMM warps (32x32 tiles, grid 2x4)
//   tid [256,384) : 4 staging warps (A hi; A_lo + Wlo in precise steps)
//   tid [384,448) : 2 scan warps (2 u-chains per thread) + I0 + output GEMVs
// Two homogeneous loops: steps 0..59 = 30 imprecise chunks x 2 KC=128 steps
// (Xhi*Whi only; softsign contraction kills old rounding error); steps 60..67 =
// 2 precise chunks x 4 KC=64 steps (full 3-term split, A_lo/B_lo via 2-deep
// PREADY/PFREE). Barrier counts: A pair 384, OUT pair 320, P pair 384.
// Each barrier: exactly one arrive-phase per sync-phase (overrun-proof).
#define TM 64
#define A_LD 136     // 128 + 8 pad (A_hi, KC=128 capable; precise uses cols 0..63)
#define A_LO_LD 72   // 64 + 8 pad
#define B_LD 136
#define O_LD 136

#define A_HI_BUF (TM * A_LD * 2)          // 17408 B
#define A_LO_BUF (TM * A_LO_LD * 2)       // 9216 B
#define BLO_BUF  (64 * B_LD * 2)          // 17408 B
#define OFF_BHI 0                          // 69632
#define OFF_AHI 69632                      // 2 bufs -> 34816
#define OFF_ALO 104448                     // 2 bufs -> 18432
#define OFF_BLO 122880                     // 2 bufs -> 34816
#define OFF_OUT 157696                     // 2 x 64*136*4 = 69632
#define OUT_ELE (TM * O_LD)
#define FUSED_SMEM 227328

#define NCHUNK 32
#define PRECISE_C 30
#define NSTEP_I 60      // imprecise steps (KC=128)
#define NSTEP_P 8       // precise steps (KC=64)

static __device__ __forceinline__ void split4(float4 v, uint2& hv, uint2& lv) {
    __nv_bfloat162 h01, h23, l01, l23;
    h01.x = __float2bfloat16(v.x); h01.y = __float2bfloat16(v.y);
    h23.x = __float2bfloat16(v.z); h23.y = __float2bfloat16(v.w);
    l01.x = __float2bfloat16(v.x - __bfloat162float(h01.x));
    l01.y = __float2bfloat16(v.y - __bfloat162float(h01.y));
    l23.x = __float2bfloat16(v.z - __bfloat162float(h23.x));
    l23.y = __float2bfloat16(v.w - __bfloat162float(h23.y));
    hv.x = *reinterpret_cast<uint32_t*>(&h01);
    hv.y = *reinterpret_cast<uint32_t*>(&h23);
    lv.x = *reinterpret_cast<uint32_t*>(&l01);
    lv.y = *reinterpret_cast<uint32_t*>(&l23);
}
static __device__ __forceinline__ uint2 pack_hi4(float4 v) {
    __nv_bfloat162 h01, h23;
    h01.x = __float2bfloat16(v.x); h01.y = __float2bfloat16(v.y);
    h23.x = __float2bfloat16(v.z); h23.y = __float2bfloat16(v.w);
    uint2 r;
    r.x = *reinterpret_cast<uint32_t*>(&h01);
    r.y = *reinterpret_cast<uint32_t*>(&h23);
    return r;
}
static __device__ __forceinline__ uint2 pack_lo4(float4 v) {
    __nv_bfloat162 l01, l23;
    l01.x = __float2bfloat16(v.x - __bfloat162float(__float2bfloat16(v.x)));
    l01.y = __float2bfloat16(v.y - __bfloat162float(__float2bfloat16(v.y)));
    l23.x = __float2bfloat16(v.z - __bfloat162float(__float2bfloat16(v.z)));
    l23.y = __float2bfloat16(v.w - __bfloat162float(__float2bfloat16(v.w)));
    uint2 r;
    r.x = *reinterpret_cast<uint32_t*>(&l01);
    r.y = *reinterpret_cast<uint32_t*>(&l23);
    return r;
}

__global__ void __launch_bounds__(448, 1) fused_kernel(
        const float* __restrict__ U,
        const float* __restrict__ X,
        const float* __restrict__ W_i,
        const float* __restrict__ R_0,
        const float* __restrict__ b_0,
        const float* __restrict__ R_z,
        const float* __restrict__ b_z,
        const float* __restrict__ R_b,
        const float* __restrict__ W_p,
        const float* __restrict__ W_d,
        float* __restrict__ out) {
    using namespace nvcuda;
    extern __shared__ __align__(16) char smc[];
    __nv_bfloat16* const Bhi  = reinterpret_cast<__nv_bfloat16*>(smc + OFF_BHI);
    float*         const outs = reinterpret_cast<float*>(smc + OFF_OUT);

    const int tid = threadIdx.x;
    const int b   = blockIdx.x >> 1;
    const int n0  = (blockIdx.x & 1) * 128;
    const float* const Xb = X + (size_t)b * T_SZ * K_SZ;

    // ---- stage resident W_hi half (warps 0-11; scan warps do I0) ----
    if (tid < 384) {
        for (int idx = tid; idx < K_SZ * 32; idx += 384) {   // 8192 float4
            int row = idx >> 5, c4 = idx & 31;
            float4 v = *reinterpret_cast<const float4*>(W_i + (size_t)row * UN + n0 + c4 * 4);
            *reinterpret_cast<uint2*>(&Bhi[row * B_LD + c4 * 4]) = pack_hi4(v);
        }
    }
    __syncthreads();

    if (tid < 256) {
        // ======================= GEMM warps (pure compute) =======================
        const int wid = tid >> 5;
        const int wm  = wid >> 2;        // 0..1 : rows of 32
        const int wn  = wid & 3;         // 0..3 : cols of 32

        wmma::fragment<wmma::accumulator, 16, 16, 16, float> acc[2][2];
        #pragma unroll
        for (int i = 0; i < 2; i++)
            #pragma unroll
            for (int j = 0; j < 2; j++) wmma::fill_fragment(acc[i][j], 0.0f);

        // ---------- loop 1: imprecise, KC=128, 2 steps per chunk ----------
        #pragma unroll 1
        for (int step = 0; step < NSTEP_I; step++) {
            const int c    = step >> 1;
            const int abuf = step & 1;
            __nv_bfloat16* const Ah = reinterpret_cast<__nv_bfloat16*>(
                smc + OFF_AHI + abuf * A_HI_BUF);
            const int krow0 = (step & 1) * 128;

            BAR_SYNC(6 + abuf, 384);     // A_READY[abuf]

            #pragma unroll
            for (int kk = 0; kk < 128; kk += 16) {
                wmma::fragment<wmma::matrix_a, 16, 16, 16, __nv_bfloat16, wmma::row_major> ah[2];
                wmma::fragment<wmma::matrix_b, 16, 16, 16, __nv_bfloat16, wmma::row_major> bh[2];
                #pragma unroll
                for (int i = 0; i < 2; i++)
                    wmma::load_matrix_sync(ah[i], &Ah[(wm * 32 + i * 16) * A_LD + kk], A_LD);
                #pragma unroll
                for (int j = 0; j < 2; j++)
                    wmma::load_matrix_sync(bh[j], &Bhi[(krow0 + kk) * B_LD + wn * 32 + j * 16], B_LD);
                #pragma unroll
                for (int i = 0; i < 2; i++)
                    #pragma unroll
                    for (int j = 0; j < 2; j++)
                        wmma::mma_sync(acc[i][j], ah[i], bh[j], acc[i][j]);
            }
            BAR_ARRIVE(8 + abuf, 384);   // A_FREE[abuf]

            if (step & 1) {
                const int ob_buf = c & 1;
                if (c >= 2) BAR_SYNC(4 + ob_buf, 320);      // OUT_FREE[buf]
                float* ob = outs + ob_buf * OUT_ELE;
                #pragma unroll
                for (int i = 0; i < 2; i++)
                    #pragma unroll
                    for (int j = 0; j < 2; j++) {
                        wmma::store_matrix_sync(&ob[(wm * 32 + i * 16) * O_LD + wn * 32 + j * 16],
                                                acc[i][j], O_LD, wmma::mem_row_major);
                        wmma::fill_fragment(acc[i][j], 0.0f);
                    }
                BAR_ARRIVE(2 + ob_buf, 320);                // OUT_READY[buf]
            }
        }

        // ---------- loop 2: precise, KC=64, 4 steps per chunk ----------
        #pragma unroll 1
        for (int ps = 0; ps < NSTEP_P; ps++) {
            const int step = NSTEP_I + ps;
            const int c    = PRECISE_C + (ps >> 2);
            const int kc   = ps & 3;
            const int abuf = step & 1;
            const int pbuf = ps & 1;
            __nv_bfloat16* const Ah = reinterpret_cast<__nv_bfloat16*>(
                smc + OFF_AHI + abuf * A_HI_BUF);
            const __nv_bfloat16* const Al = reinterpret_cast<const __nv_bfloat16*>(
                smc + OFF_ALO + pbuf * A_LO_BUF);
            const __nv_bfloat16* const Bl = reinterpret_cast<const __nv_bfloat16*>(
                smc + OFF_BLO + pbuf * BLO_BUF);

            BAR_SYNC(6 + abuf, 384);     // A_READY[abuf]
            BAR_SYNC(12 + pbuf, 384);    // PREADY[pbuf]

            #pragma unroll
            for (int kk = 0; kk < 64; kk += 16) {
                const int krow = kc * 64 + kk;
                wmma::fragment<wmma::matrix_a, 16, 16, 16, __nv_bfloat16, wmma::row_major> ah[2], al[2];
                wmma::fragment<wmma::matrix_b, 16, 16, 16, __nv_bfloat16, wmma::row_major> bh[2], bl[2];
                #pragma unroll
                for (int i = 0; i < 2; i++) {
                    wmma::load_matrix_sync(ah[i], &Ah[(wm * 32 + i * 16) * A_LD + kk], A_LD);
                    wmma::load_matrix_sync(al[i], &Al[(wm * 32 + i * 16) * A_LO_LD + kk], A_LO_LD);
                }
                #pragma unroll
                for (int j = 0; j < 2; j++) {
                    wmma::load_matrix_sync(bh[j], &Bhi[krow * B_LD + wn * 32 + j * 16], B_LD);
                    wmma::load_matrix_sync(bl[j], &Bl[kk * B_LD + wn * 32 + j * 16], B_LD);
                }
                #pragma unroll
                for (int i = 0; i < 2; i++)
                    #pragma unroll
                    for (int j = 0; j < 2; j++) {
                        wmma::mma_sync(acc[i][j], ah[i], bh[j], acc[i][j]);   // Xhi*Whi
                        wmma::mma_sync(acc[i][j], al[i], bh[j], acc[i][j]);   // Xlo*Whi
                        wmma::mma_sync(acc[i][j], ah[i], bl[j], acc[i][j]);   // Xhi*Wlo
                    }
            }
            BAR_ARRIVE(8 + abuf, 384);   // A_FREE[abuf]
            BAR_ARRIVE(14 + pbuf, 384);  // PFREE[pbuf]

            if (kc == 3) {
                const int ob_buf = c & 1;
                BAR_SYNC(4 + ob_buf, 320);                  // OUT_FREE[buf] (c>=30)
                float* ob = outs + ob_buf * OUT_ELE;
                #pragma unroll
                for (int i = 0; i < 2; i++)
                    #pragma unroll
                    for (int j = 0; j < 2; j++) {
                        wmma::store_matrix_sync(&ob[(wm * 32 + i * 16) * O_LD + wn * 32 + j * 16],
                                                acc[i][j], O_LD, wmma::mem_row_major);
                        wmma::fill_fragment(acc[i][j], 0.0f);
                    }
                BAR_ARRIVE(2 + ob_buf, 320);                // OUT_READY[buf]
            }
        }
    } else if (tid < 384) {
        // ================= staging warps (128 threads) =================
        const int st = tid - 256;        // 0..127

        // loop 1 indexing: 64 rows x 32 float4 = 2048 / 128 thr = 16 each
        int rowv[16], c4v[16];
        #pragma unroll
        for (int r = 0; r < 16; r++) {
            int i = r * 128 + st;
            rowv[r] = i >> 5;
            c4v[r]  = i & 31;
        }
        float4 xr[16];
        #pragma unroll
        for (int r = 0; r < 16; r++)
            xr[r] = *reinterpret_cast<const float4*>(
                Xb + (size_t)rowv[r] * K_SZ + c4v[r] * 4);

        // ---------- loop 1: imprecise, KC=128 ----------
        #pragma unroll 1
        for (int step = 0; step < NSTEP_I; step++) {
            const int abuf = step & 1;
            __nv_bfloat16* const Ah = reinterpret_cast<__nv_bfloat16*>(
                smc + OFF_AHI + abuf * A_HI_BUF);

            if (step >= 2) BAR_SYNC(8 + abuf, 384);   // A_FREE[abuf]
            #pragma unroll
            for (int r = 0; r < 16; r++)
                *reinterpret_cast<uint2*>(&Ah[rowv[r] * A_LD + c4v[r] * 4]) = pack_hi4(xr[r]);
            BAR_ARRIVE(6 + abuf, 384);                // A_READY[abuf]

            if (step + 1 < NSTEP_I) {
                const int nc = (step + 1) >> 1;
                const int nk = ((step + 1) & 1) * 128;
                const float* src = Xb + (size_t)(nc * TM) * K_SZ + nk;
                #pragma unroll
                for (int r = 0; r < 16; r++)
                    xr[r] = *reinterpret_cast<const float4*>(
                        src + (size_t)rowv[r] * K_SZ + c4v[r] * 4);
            }
        }

        // ---------- loop 2: precise, KC=64 (direct loads, MLP-covered) ----------
        // X: 64 rows x 16 float4 = 1024 / 128 = 8 each. Wlo: 2048 / 128 = 16 each.
        #pragma unroll 1
        for (int ps = 0; ps < NSTEP_P; ps++) {
            const int step = NSTEP_I + ps;
            const int c    = PRECISE_C + (ps >> 2);
            const int kc   = ps & 3;
            const int abuf = step & 1;
            const int pbuf = ps & 1;
            __nv_bfloat16* const Ah = reinterpret_cast<__nv_bfloat16*>(
                smc + OFF_AHI + abuf * A_HI_BUF);
            __nv_bfloat16* const Al = reinterpret_cast<__nv_bfloat16*>(
                smc + OFF_ALO + pbuf * A_LO_BUF);
            __nv_bfloat16* const Bl = reinterpret_cast<__nv_bfloat16*>(
                smc + OFF_BLO + pbuf * BLO_BUF);

            BAR_SYNC(8 + abuf, 384);                  // A_FREE[abuf] (step>=2 always)
            if (ps >= 2) BAR_SYNC(14 + pbuf, 384);    // PFREE[pbuf]

            const float* const xsrc = Xb + (size_t)(c * TM) * K_SZ + kc * 64;
            float4 xv[8];
            #pragma unroll
            for (int r = 0; r < 8; r++) {
                int i = r * 128 + st;
                xv[r] = *reinterpret_cast<const float4*>(
                    xsrc + (size_t)(i >> 4) * K_SZ + (i & 15) * 4);
            }
            float4 wv[16];
            #pragma unroll
            for (int r = 0; r < 16; r++) {
                int i = r * 128 + st;
                wv[r] = *reinterpret_cast<const float4*>(
                    W_i + (size_t)(kc * 64 + (i >> 5)) * UN + n0 + (i & 31) * 4);
            }
            #pragma unroll
            for (int r = 0; r < 8; r++) {
                int i = r * 128 + st;
                int row = i >> 4, c4 = i & 15;
                uint2 hv, lv;
                split4(xv[r], hv, lv);
                *reinterpret_cast<uint2*>(&Ah[row * A_LD + c4 * 4])    = hv;
                *reinterpret_cast<uint2*>(&Al[row * A_LO_LD + c4 * 4]) = lv;
            }
            #pragma unroll
            for (int r = 0; r < 16; r++) {
                int i = r * 128 + st;
                int row = i >> 5, cc = i & 31;
                *reinterpret_cast<uint2*>(&Bl[row * B_LD + cc * 4]) = pack_lo4(wv[r]);
            }
            BAR_ARRIVE(6 + abuf, 384);                // A_READY[abuf]
            BAR_ARRIVE(12 + pbuf, 384);               // PREADY[pbuf]
        }
    } else {
        // ============ scan warps: I recurrence + I0 + all output GEMVs ============
        const int u0 = (tid - 384) * 2;   // 0,2,..,126 (local)
        const int ug = n0 + u0;           // global unit column (even)

        float Ia = b_0[ug];
        float Ib = b_0[ug + 1];
        {
            const float* R0c = R_0 + ug;            // R_0 is [K_SZ][512]
            const float* Ubp = U + (size_t)b * K_SZ;
            #pragma unroll 8
            for (int k = 0; k < K_SZ; k++) {
                float uv = Ubp[k];
                Ia = fmaf(uv, R0c[(size_t)k * 512],     Ia);
                Ib = fmaf(uv, R0c[(size_t)k * 512 + 1], Ib);
            }
        }

        float ub_a = 0.f, ub_b = 0.f;
        float zp_a = b_z[3 * ug],     zi_a = b_z[3 * ug + 1], zd_a = b_z[3 * ug + 2];
        float zp_b = b_z[3 * ug + 3], zi_b = b_z[3 * ug + 4], zd_b = b_z[3 * ug + 5];
        float p_a = 0.f, p_b = 0.f, d_a = 0.f, d_b = 0.f;
        const float* const Ubp = U + (size_t)b * K_SZ;
        const float* const xlp = Xb + (size_t)(T_SZ - 1) * K_SZ;
        const float* const xpp = Xb + (size_t)(T_SZ - 2) * K_SZ;

        #pragma unroll 1
        for (int c = 0; c < NCHUNK; c++) {
            const int ob_buf = c & 1;
            BAR_SYNC(2 + ob_buf, 320);                      // OUT_READY[buf]
            const float* ob = outs + ob_buf * OUT_ELE;
            const float2* obp = reinterpret_cast<const float2*>(ob) + (u0 >> 1);
            float2 v  = obp[0];
            float2 vn = obp[O_LD / 2];
            #pragma unroll 8
            for (int t = 0; t < TM; t++) {
                float za = Ia + v.x;
                float zb = Ib + v.y;
                v = vn;
                if (t + 2 < TM) vn = obp[(size_t)(t + 2) * (O_LD / 2)];
                Ia = __fdividef(za, 1.0f + fabsf(za));
                Ib = __fdividef(zb, 1.0f + fabsf(zb));
            }
            BAR_ARRIVE(4 + ob_buf, 320);                    // OUT_FREE[buf]

            // ---- epilogue k-slice [8c, 8c+8) (hidden in scan slack) ----
            #pragma unroll
            for (int kk = 0; kk < 8; kk++) {
                const int k = c * 8 + kk;
                float uv  = Ubp[k];
                float xlv = xlp[k];
                float dxv = xlv - xpp[k];
                float2 rb  = *reinterpret_cast<const float2*>(R_b + (size_t)k * UN + ug);
                float2 rz0 = *reinterpret_cast<const float2*>(R_z + (size_t)k * 768 + 3 * ug);
                float2 rz1 = *reinterpret_cast<const float2*>(R_z + (size_t)k * 768 + 3 * ug + 2);
                float2 rz2 = *reinterpret_cast<const float2*>(R_z + (size_t)k * 768 + 3 * ug + 4);
                float2 wp  = *reinterpret_cast<const float2*>(W_p + (size_t)k * UN + ug);
                float2 wd  = *reinterpret_cast<const float2*>(W_d + (size_t)k * UN + ug);
                ub_a = fmaf(uv, rb.x, ub_a);   ub_b = fmaf(uv, rb.y, ub_b);
                zp_a = fmaf(uv, rz0.x, zp_a);  zi_a = fmaf(uv, rz0.y, zi_a);
                zd_a = fmaf(uv, rz1.x, zd_a);  zp_b = fmaf(uv, rz1.y, zp_b);
                zi_b = fmaf(uv, rz2.x, zi_b);  zd_b = fmaf(uv, rz2.y, zd_b);
                p_a  = fmaf(xlv, wp.x, p_a);   p_b  = fmaf(xlv, wp.y, p_b);
                d_a  = fmaf(dxv, wd.x, d_a);   d_b  = fmaf(dxv, wd.y, d_b);
            }
        }

        float Pa = softsign_exact(ub_a + p_a);
        float Pb = softsign_exact(ub_b + p_b);
        float Da = softsign_exact(d_a);
        float Db = softsign_exact(d_b);
        float2 r;
        r.x = zp_a * Pa + zi_a * Ia + zd_a * Da;
        r.y = zp_b * Pb + zi_b * Ib + zd_b * Db;
        *reinterpret_cast<float2*>(out + (size_t)b * UN + ug) = r;
    }
}

// ---------------- launcher ----------------
extern "C" void kernel_launch(void* const* d_in, const int* in_sizes, int n_in,
                              void* d_out, int out_size) {
    const float* U   = (const float*)d_in[0];
    const float* X   = (const float*)d_in[1];
    const float* R_z = (const float*)d_in[2];
    const float* b_z = (const float*)d_in[3];
    const float* R_0 = (const float*)d_in[4];
    const float* b_0 = (const float*)d_in[5];
    const float* R_b = (const float*)d_in[6];
    const float* W_p = (const float*)d_in[7];
    const float* W_i = (const float*)d_in[8];
    const float* W_d = (const float*)d_in[9];
    float* out = (float*)d_out;

    cudaFuncSetAttribute(fused_kernel,
                         cudaFuncAttributeMaxDynamicSharedMemorySize, FUSED_SMEM);

    fused_kernel<<<2 * B_SZ, 448, FUSED_SMEM>>>(U, X, W_i, R_0, b_0,
                                                R_z, b_z, R_b, W_p, W_d, out);
}